// round 14
// baseline (speedup 1.0000x reference)
#include <cuda_runtime.h>
#include <stdint.h>

// Pre-emphasis IIR y[i] = x[i] + 0.85*y[i-1]; out[o] = float(clip_int16(32768*y[o+91])),
// out[N-91..] = 0.
// R14: R13's 8-sample/lane warp Kogge-Stone, scaled to 16 warps/block (512 thr):
// 31 stored windows -> tile 7936 (warmup overhead 3.2%), 48 warps/SM (75% occ)
// to feed DRAM (R13 was latency-bound at 40 warps). Uniform broadcast ext load.

namespace {
constexpr int   kWarps   = 16;
constexpr int   kThreads = kWarps * 32;          // 512
constexpr int   kWin     = 256;                  // outputs per window (8/lane)
constexpr int   kTile    = (2 * kWarps - 1) * kWin;  // 31 windows = 7936
constexpr int   kSkip    = 91;
constexpr float C1       = 0.85f;

constexpr float cp(int k) {
    float r = 1.0f;
    for (int i = 0; i < k; ++i) r *= 0.85f;
    return r;
}
constexpr float A1 = cp(1), A2 = cp(2), A3 = cp(3), A4 = cp(4);
constexpr float A5 = cp(5), A6 = cp(6), A7 = cp(7), A8 = cp(8);
constexpr float W1 = cp(8), W2 = cp(16), W3 = cp(32), W4 = cp(64), W5 = cp(128);
}

// Saturating truncate-toward-zero to int16 range, back to float.
// Matches clip(-32768,32767) + astype(int16) exactly (f32->s16 cvt saturates).
__device__ __forceinline__ float q16(float v) {
    short q; asm("cvt.rzi.s16.f32 %0, %1;" : "=h"(q) : "f"(v));
    float r; asm("cvt.rn.f32.s16 %0, %1;" : "=f"(r) : "h"(q));
    return r;
}

template <bool EDGE>
__device__ __forceinline__ float4 ld4(const float* __restrict__ x, int e0, int n) {
    if (!EDGE) return *reinterpret_cast<const float4*>(x + e0);
    float4 v;
    v.x = (e0 + 0 >= 0 && e0 + 0 < n) ? x[e0 + 0] : 0.0f;
    v.y = (e0 + 1 >= 0 && e0 + 1 < n) ? x[e0 + 1] : 0.0f;
    v.z = (e0 + 2 >= 0 && e0 + 2 < n) ? x[e0 + 2] : 0.0f;
    v.w = (e0 + 3 >= 0 && e0 + 3 < n) ? x[e0 + 3] : 0.0f;
    return v;
}

// 4-level weighted Kogge-Stone (c^128 level dropped; error < 1e-9 relative)
__device__ __forceinline__ void ks4(float yEnd, int l, float& pex, float& P31) {
    const unsigned FULL = 0xffffffffu;
    float P = yEnd, u;
    u = __shfl_up_sync(FULL, P, 1); P = (l >= 1) ? fmaf(W1, u, P) : P;
    u = __shfl_up_sync(FULL, P, 2); P = (l >= 2) ? fmaf(W2, u, P) : P;
    u = __shfl_up_sync(FULL, P, 4); P = (l >= 4) ? fmaf(W3, u, P) : P;
    u = __shfl_up_sync(FULL, P, 8); P = (l >= 8) ? fmaf(W4, u, P) : P;
    float pe = __shfl_up_sync(FULL, P, 1);
    pex = (l == 0) ? 0.0f : pe;
    P31 = __shfl_sync(FULL, P, 31);
}

__device__ __forceinline__ void scan8(const float4& u, const float4& v,
                                      float nx, float ny, float nz, float* y) {
    // lane samples (post +3 realign): {u.w, v.x, v.y, v.z, v.w, nx, ny, nz}
    y[0] = u.w;
    y[1] = fmaf(C1, y[0], v.x);
    y[2] = fmaf(C1, y[1], v.y);
    y[3] = fmaf(C1, y[2], v.z);
    y[4] = fmaf(C1, y[3], v.w);
    y[5] = fmaf(C1, y[4], nx);
    y[6] = fmaf(C1, y[5], ny);
    y[7] = fmaf(C1, y[6], nz);
}

template <bool EDGE>
__device__ __forceinline__ void emit(float* __restrict__ out, const float* y,
                                     float E, int ob, int l, int n, int nout) {
    float o0 = q16(32768.0f * fmaf(A1, E, y[0]));
    float o1 = q16(32768.0f * fmaf(A2, E, y[1]));
    float o2 = q16(32768.0f * fmaf(A3, E, y[2]));
    float o3 = q16(32768.0f * fmaf(A4, E, y[3]));
    float o4 = q16(32768.0f * fmaf(A5, E, y[4]));
    float o5 = q16(32768.0f * fmaf(A6, E, y[5]));
    float o6 = q16(32768.0f * fmaf(A7, E, y[6]));
    float o7 = q16(32768.0f * fmaf(A8, E, y[7]));
    if (!EDGE) {
        float4* o4p = reinterpret_cast<float4*>(out);
        const int idx = (ob >> 2) + 2 * l;
        o4p[idx]     = make_float4(o0, o1, o2, o3);
        o4p[idx + 1] = make_float4(o4, o5, o6, o7);
    } else {
        const int oi = ob + 8 * l;
        const int zf = n - kSkip;                // outputs at/after this are 0
        float v[8] = {o0, o1, o2, o3, o4, o5, o6, o7};
        #pragma unroll
        for (int e = 0; e < 8; ++e)
            if (oi + e < nout)
                out[oi + e] = (oi + e < zf) ? v[e] : 0.0f;
    }
}

template <bool EDGE>
__device__ __forceinline__ void block_body(const float* __restrict__ x,
                                           float* __restrict__ out,
                                           int n, int nout, int O, int w, int l)
{
    __shared__ float sLast[kWarps];
    const unsigned FULL = 0xffffffffu;

    // warp w owns windows jA = 2w-1 (w=0: warmup, unstored) and jB = 2w.
    // Window j lane-l loads: x[O + 256j + 88 + 8l .. +8)
    const int baseA = O + kWin * (2 * w - 1) + 88 + 8 * l;
    float4 uA = ld4<EDGE>(x, baseA, n);
    float4 vA = ld4<EDGE>(x, baseA + 4, n);
    float4 uB = ld4<EDGE>(x, baseA + kWin, n);
    float4 vB = ld4<EDGE>(x, baseA + kWin + 4, n);
    // window B realign tail: first float4 of window 2w+1. Uniform address ->
    // single broadcast wavefront (only lane 31's value is consumed).
    float4 ext = ld4<EDGE>(x, O + kWin * (2 * w + 1) + 88, n);

    // c^(8l) via bit decomposition
    float c8l = 1.0f;
    if (l & 1)  c8l *= W1;
    if (l & 2)  c8l *= W2;
    if (l & 4)  c8l *= W3;
    if (l & 8)  c8l *= W4;
    if (l & 16) c8l *= W5;

    // window A realign: next lane's u.{x,y,z}; lane 31 takes window B's lane-0 u
    // via select-then-shfl from lane (l+1)&31.
    const int src = (l + 1) & 31;
    float tx = (l == 0) ? uB.x : uA.x;
    float ty = (l == 0) ? uB.y : uA.y;
    float tz = (l == 0) ? uB.z : uA.z;
    float nax = __shfl_sync(FULL, tx, src);
    float nay = __shfl_sync(FULL, ty, src);
    float naz = __shfl_sync(FULL, tz, src);

    float yA[8];
    scan8(uA, vA, nax, nay, naz, yA);
    float peA, PA;
    ks4(yA[7], l, peA, PA);

    // window B realign: shfl_down; lane 31 uses ext
    float nbx = __shfl_down_sync(FULL, uB.x, 1);
    float nby = __shfl_down_sync(FULL, uB.y, 1);
    float nbz = __shfl_down_sync(FULL, uB.z, 1);
    if (l == 31) { nbx = ext.x; nby = ext.y; nbz = ext.z; }

    float yB[8];
    scan8(uB, vB, nbx, nby, nbz, yB);
    float peB, PB;
    ks4(yB[7], l, peB, PB);

    if (l == 0) sLast[w] = PB;
    __syncthreads();

    // entering state of window jA = P31 of window jA-1 (c^256 term dropped)
    const float S = (w == 0) ? 0.0f : sLast[w - 1];

    if (w > 0)                                    // window A (skip warmup)
        emit<EDGE>(out, yA, fmaf(c8l, S, peA), O + (2 * w - 1) * kWin, l, n, nout);
    // window B: entering state = PA
    emit<EDGE>(out, yB, fmaf(c8l, PA, peB), O + 2 * w * kWin, l, n, nout);
}

__global__ __launch_bounds__(kThreads, 3)
void preemph_f32_kernel(const float* __restrict__ x, float* __restrict__ out,
                        int n, int nout)
{
    const int b = blockIdx.x;
    const int w = threadIdx.x >> 5;
    const int l = threadIdx.x & 31;
    const int O = b * kTile;
    if (O >= nout) return;
    // interior: min load O-168 >= 0 (b>=1); max load O + kTile + 91;
    // tile entirely before nout and the zero tail.
    const bool edge = (b == 0) || (O + kTile + 92 > n) || (O + kTile > nout)
                   || (O + kTile > n - kSkip);
    if (edge) block_body<true >(x, out, n, nout, O, w, l);
    else      block_body<false>(x, out, n, nout, O, w, l);
}

extern "C" void kernel_launch(void* const* d_in, const int* in_sizes, int n_in,
                              void* d_out, int out_size) {
    const float* x = (const float*)d_in[0];
    float* out = (float*)d_out;
    const int n = in_sizes[0];
    const int grid = (out_size + kTile - 1) / kTile;
    preemph_f32_kernel<<<grid, kThreads>>>(x, out, n, out_size);
}

// round 15
// speedup vs baseline: 1.0610x; 1.0610x over previous
#include <cuda_runtime.h>
#include <stdint.h>

// Pre-emphasis IIR y[i] = x[i] + 0.85*y[i-1]; out[o] = float(clip_int16(32768*y[o+91])),
// out[N-91..] = 0.
// R15: fully independent warps — no smem, no barriers. Each warp: 1024 outputs =
// 4 windows of 256 (8 samples/lane). Entering state from a 128-sample weighted
// dot product (3 FMA/lane + 5-shfl butterfly; trunc err c^128 ~ 2e-10); windows
// chain in-registers via P31. 11 up-front LDG.128/lane (MLP 11), 41 shfl/1024 out.

namespace {
constexpr int   kThreads = 256;                 // 8 warps
constexpr int   kWin     = 256;                 // outputs per window (8/lane)
constexpr int   kWpw     = 4;                   // windows per warp
constexpr int   kSeg     = kWin * kWpw;         // 1024 outputs per warp
constexpr int   kSkip    = 91;
constexpr float C1       = 0.85f;

constexpr float cp(int k) {
    float r = 1.0f;
    for (int i = 0; i < k; ++i) r *= 0.85f;
    return r;
}
// correction: true y_k = y_k + E * c^(k+1) within an 8-sample lane chunk
constexpr float A1 = cp(1), A2 = cp(2), A3 = cp(3), A4 = cp(4);
constexpr float A5 = cp(5), A6 = cp(6), A7 = cp(7), A8 = cp(8);
// Kogge-Stone merge weights (8 samples/lane)
constexpr float W1 = cp(8), W2 = cp(16), W3 = cp(32), W4 = cp(64), W5 = cp(128);
// warmup lane-scale decomposition weights (4 samples/lane)
constexpr float V1 = cp(4), V2 = cp(8), V3 = cp(16), V4 = cp(32), V5 = cp(64);
constexpr float C2 = cp(2), C3 = cp(3);
}

// Saturating truncate-toward-zero to int16 range, back to float.
// Matches clip(-32768,32767) + astype(int16) exactly (f32->s16 cvt saturates).
__device__ __forceinline__ float q16(float v) {
    short q; asm("cvt.rzi.s16.f32 %0, %1;" : "=h"(q) : "f"(v));
    float r; asm("cvt.rn.f32.s16 %0, %1;" : "=f"(r) : "h"(q));
    return r;
}

template <bool EDGE>
__device__ __forceinline__ float4 ld4(const float* __restrict__ x, int e0, int n) {
    if (!EDGE) return *reinterpret_cast<const float4*>(x + e0);
    float4 v;
    v.x = (e0 + 0 >= 0 && e0 + 0 < n) ? x[e0 + 0] : 0.0f;
    v.y = (e0 + 1 >= 0 && e0 + 1 < n) ? x[e0 + 1] : 0.0f;
    v.z = (e0 + 2 >= 0 && e0 + 2 < n) ? x[e0 + 2] : 0.0f;
    v.w = (e0 + 3 >= 0 && e0 + 3 < n) ? x[e0 + 3] : 0.0f;
    return v;
}

// 4-level weighted Kogge-Stone (c^128 level dropped; error < 1e-9 relative)
__device__ __forceinline__ void ks4(float yEnd, int l, float& pex, float& P31) {
    const unsigned FULL = 0xffffffffu;
    float P = yEnd, u;
    u = __shfl_up_sync(FULL, P, 1); P = (l >= 1) ? fmaf(W1, u, P) : P;
    u = __shfl_up_sync(FULL, P, 2); P = (l >= 2) ? fmaf(W2, u, P) : P;
    u = __shfl_up_sync(FULL, P, 4); P = (l >= 4) ? fmaf(W3, u, P) : P;
    u = __shfl_up_sync(FULL, P, 8); P = (l >= 8) ? fmaf(W4, u, P) : P;
    float pe = __shfl_up_sync(FULL, P, 1);
    pex = (l == 0) ? 0.0f : pe;
    P31 = __shfl_sync(FULL, P, 31);
}

__device__ __forceinline__ void scan8(const float4& u, const float4& v,
                                      float nx, float ny, float nz, float* y) {
    // lane samples (post +3 realign): {u.w, v.x, v.y, v.z, v.w, nx, ny, nz}
    y[0] = u.w;
    y[1] = fmaf(C1, y[0], v.x);
    y[2] = fmaf(C1, y[1], v.y);
    y[3] = fmaf(C1, y[2], v.z);
    y[4] = fmaf(C1, y[3], v.w);
    y[5] = fmaf(C1, y[4], nx);
    y[6] = fmaf(C1, y[5], ny);
    y[7] = fmaf(C1, y[6], nz);
}

template <bool EDGE>
__device__ __forceinline__ void emit(float* __restrict__ out, const float* y,
                                     float E, int ob, int l, int n, int nout) {
    float o0 = q16(32768.0f * fmaf(A1, E, y[0]));
    float o1 = q16(32768.0f * fmaf(A2, E, y[1]));
    float o2 = q16(32768.0f * fmaf(A3, E, y[2]));
    float o3 = q16(32768.0f * fmaf(A4, E, y[3]));
    float o4 = q16(32768.0f * fmaf(A5, E, y[4]));
    float o5 = q16(32768.0f * fmaf(A6, E, y[5]));
    float o6 = q16(32768.0f * fmaf(A7, E, y[6]));
    float o7 = q16(32768.0f * fmaf(A8, E, y[7]));
    if (!EDGE) {
        float4* o4p = reinterpret_cast<float4*>(out);
        const int idx = (ob >> 2) + 2 * l;
        o4p[idx]     = make_float4(o0, o1, o2, o3);
        o4p[idx + 1] = make_float4(o4, o5, o6, o7);
    } else {
        const int oi = ob + 8 * l;
        const int zf = n - kSkip;                // outputs at/after this are 0
        float v[8] = {o0, o1, o2, o3, o4, o5, o6, o7};
        #pragma unroll
        for (int e = 0; e < 8; ++e)
            if (oi + e < nout)
                out[oi + e] = (oi + e < zf) ? v[e] : 0.0f;
    }
}

template <bool EDGE>
__device__ __forceinline__ void warp_body(const float* __restrict__ x,
                                          float* __restrict__ out,
                                          int n, int nout, int O, int l)
{
    const unsigned FULL = 0xffffffffu;

    // ---- all loads up front (MLP) ----
    // warmup: 128 samples x[O-40 .. O+88) -> state before y index O+91,
    // head terms x[O+88..91) from a uniform broadcast load.
    float4 wm = ld4<EDGE>(x, O - 40 + 4 * l, n);
    float4 hd = ld4<EDGE>(x, O + 88, n);               // uniform line
    float4 u[kWpw], v[kWpw];
    #pragma unroll
    for (int j = 0; j < kWpw; ++j) {
        const int base = O + kWin * j + 88 + 8 * l;
        u[j] = ld4<EDGE>(x, base, n);
        v[j] = ld4<EDGE>(x, base + 4, n);
    }
    float4 ext = ld4<EDGE>(x, O + kWin * kWpw + 88, n);  // uniform line

    // ---- per-lane constants ----
    float c8l = 1.0f;                    // c^(8l)
    if (l & 1)  c8l *= W1;
    if (l & 2)  c8l *= W2;
    if (l & 4)  c8l *= W3;
    if (l & 8)  c8l *= W4;
    if (l & 16) c8l *= W5;
    const int m = 31 - l;
    float c4m = C3;                      // c^(127-4l) = c^3 * c^(4m)
    if (m & 1)  c4m *= V1;
    if (m & 2)  c4m *= V2;
    if (m & 4)  c4m *= V3;
    if (m & 8)  c4m *= V4;
    if (m & 16) c4m *= V5;

    // ---- warmup state: E = sum_{d=0}^{127} c^d x[O+90-d] ----
    float q = fmaf(C1, fmaf(C1, fmaf(C1, wm.x, wm.y), wm.z), wm.w);
    float p = q * c4m;
    p += __shfl_xor_sync(FULL, p, 16);
    p += __shfl_xor_sync(FULL, p, 8);
    p += __shfl_xor_sync(FULL, p, 4);
    p += __shfl_xor_sync(FULL, p, 2);
    p += __shfl_xor_sync(FULL, p, 1);
    float S = p + fmaf(C2, hd.x, fmaf(C1, hd.y, hd.z));

    // ---- 4 windows, carried in registers ----
    const int src = (l + 1) & 31;
    #pragma unroll
    for (int j = 0; j < kWpw; ++j) {
        // realign +3: next lane's u.{x,y,z}; lane 31 takes next window's lane-0 u
        // (or ext, uniform) via select-then-shfl.
        float tx = (l == 0) ? ((j < kWpw - 1) ? u[j + 1].x : ext.x) : u[j].x;
        float ty = (l == 0) ? ((j < kWpw - 1) ? u[j + 1].y : ext.y) : u[j].y;
        float tz = (l == 0) ? ((j < kWpw - 1) ? u[j + 1].z : ext.z) : u[j].z;
        float nx = __shfl_sync(FULL, tx, src);
        float ny = __shfl_sync(FULL, ty, src);
        float nz = __shfl_sync(FULL, tz, src);

        float y[8];
        scan8(u[j], v[j], nx, ny, nz, y);
        float pex, P31;
        ks4(y[7], l, pex, P31);

        float E = fmaf(c8l, S, pex);
        S = P31;                         // c^256 * S term ~ 1e-19: dropped
        emit<EDGE>(out, y, E, O + j * kWin, l, n, nout);
    }
}

__global__ __launch_bounds__(kThreads)
void preemph_f32_kernel(const float* __restrict__ x, float* __restrict__ out,
                        int n, int nout)
{
    const int wid = (blockIdx.x * kThreads + threadIdx.x) >> 5;
    const int l   = threadIdx.x & 31;
    const int O   = wid * kSeg;
    if (O >= nout) return;
    // interior: warmup load O-40 >= 0; max read O + 1024 + 92 <= n;
    // outputs [O, O+1024) inside nout and before the zero tail (n-91).
    const bool edge = (O == 0) || (O + kSeg + 92 > n) || (O + kSeg > nout)
                   || (O + kSeg > n - kSkip);
    if (edge) warp_body<true >(x, out, n, nout, O, l);
    else      warp_body<false>(x, out, n, nout, O, l);
}

extern "C" void kernel_launch(void* const* d_in, const int* in_sizes, int n_in,
                              void* d_out, int out_size) {
    const float* x = (const float*)d_in[0];
    float* out = (float*)d_out;
    const int n = in_sizes[0];
    const int warps = (out_size + kSeg - 1) / kSeg;
    const int grid = (warps + (kThreads / 32) - 1) / (kThreads / 32);
    preemph_f32_kernel<<<grid, kThreads>>>(x, out, n, out_size);
}

// round 16
// speedup vs baseline: 1.0993x; 1.0360x over previous
#include <cuda_runtime.h>
#include <stdint.h>

// Pre-emphasis IIR y[i] = x[i] + 0.85*y[i-1]; out[o] = float(clip_int16(32768*y[o+91])),
// out[N-91..] = 0.
// R16: R15 (barrier-free independent warps, 8 samples/lane, warmup dot product,
// in-register P31 window chain) with 3 windows/warp instead of 4: peak live data
// 24 regs -> launch_bounds(256,5) gives 40 warps/SM (R15: 63 regs, 26 warps).
// Warmup re-reads (16.7%) are L2 hits (neighbor warp streams the same lines).

namespace {
constexpr int   kThreads = 256;                 // 8 warps
constexpr int   kWin     = 256;                 // outputs per window (8/lane)
constexpr int   kWpw     = 3;                   // windows per warp
constexpr int   kSeg     = kWin * kWpw;         // 768 outputs per warp
constexpr int   kSkip    = 91;
constexpr float C1       = 0.85f;

constexpr float cp(int k) {
    float r = 1.0f;
    for (int i = 0; i < k; ++i) r *= 0.85f;
    return r;
}
// correction: true y_k = y_k + E * c^(k+1) within an 8-sample lane chunk
constexpr float A1 = cp(1), A2 = cp(2), A3 = cp(3), A4 = cp(4);
constexpr float A5 = cp(5), A6 = cp(6), A7 = cp(7), A8 = cp(8);
// Kogge-Stone merge weights (8 samples/lane)
constexpr float W1 = cp(8), W2 = cp(16), W3 = cp(32), W4 = cp(64), W5 = cp(128);
// warmup lane-scale decomposition weights (4 samples/lane)
constexpr float V1 = cp(4), V2 = cp(8), V3 = cp(16), V4 = cp(32), V5 = cp(64);
constexpr float C2 = cp(2), C3 = cp(3);
}

// Saturating truncate-toward-zero to int16 range, back to float.
// Matches clip(-32768,32767) + astype(int16) exactly (f32->s16 cvt saturates).
__device__ __forceinline__ float q16(float v) {
    short q; asm("cvt.rzi.s16.f32 %0, %1;" : "=h"(q) : "f"(v));
    float r; asm("cvt.rn.f32.s16 %0, %1;" : "=f"(r) : "h"(q));
    return r;
}

template <bool EDGE>
__device__ __forceinline__ float4 ld4(const float* __restrict__ x, int e0, int n) {
    if (!EDGE) return *reinterpret_cast<const float4*>(x + e0);
    float4 v;
    v.x = (e0 + 0 >= 0 && e0 + 0 < n) ? x[e0 + 0] : 0.0f;
    v.y = (e0 + 1 >= 0 && e0 + 1 < n) ? x[e0 + 1] : 0.0f;
    v.z = (e0 + 2 >= 0 && e0 + 2 < n) ? x[e0 + 2] : 0.0f;
    v.w = (e0 + 3 >= 0 && e0 + 3 < n) ? x[e0 + 3] : 0.0f;
    return v;
}

// 4-level weighted Kogge-Stone (c^128 level dropped; error < 1e-9 relative)
__device__ __forceinline__ void ks4(float yEnd, int l, float& pex, float& P31) {
    const unsigned FULL = 0xffffffffu;
    float P = yEnd, u;
    u = __shfl_up_sync(FULL, P, 1); P = (l >= 1) ? fmaf(W1, u, P) : P;
    u = __shfl_up_sync(FULL, P, 2); P = (l >= 2) ? fmaf(W2, u, P) : P;
    u = __shfl_up_sync(FULL, P, 4); P = (l >= 4) ? fmaf(W3, u, P) : P;
    u = __shfl_up_sync(FULL, P, 8); P = (l >= 8) ? fmaf(W4, u, P) : P;
    float pe = __shfl_up_sync(FULL, P, 1);
    pex = (l == 0) ? 0.0f : pe;
    P31 = __shfl_sync(FULL, P, 31);
}

__device__ __forceinline__ void scan8(const float4& u, const float4& v,
                                      float nx, float ny, float nz, float* y) {
    // lane samples (post +3 realign): {u.w, v.x, v.y, v.z, v.w, nx, ny, nz}
    y[0] = u.w;
    y[1] = fmaf(C1, y[0], v.x);
    y[2] = fmaf(C1, y[1], v.y);
    y[3] = fmaf(C1, y[2], v.z);
    y[4] = fmaf(C1, y[3], v.w);
    y[5] = fmaf(C1, y[4], nx);
    y[6] = fmaf(C1, y[5], ny);
    y[7] = fmaf(C1, y[6], nz);
}

template <bool EDGE>
__device__ __forceinline__ void emit(float* __restrict__ out, const float* y,
                                     float E, int ob, int l, int n, int nout) {
    float o0 = q16(32768.0f * fmaf(A1, E, y[0]));
    float o1 = q16(32768.0f * fmaf(A2, E, y[1]));
    float o2 = q16(32768.0f * fmaf(A3, E, y[2]));
    float o3 = q16(32768.0f * fmaf(A4, E, y[3]));
    float o4 = q16(32768.0f * fmaf(A5, E, y[4]));
    float o5 = q16(32768.0f * fmaf(A6, E, y[5]));
    float o6 = q16(32768.0f * fmaf(A7, E, y[6]));
    float o7 = q16(32768.0f * fmaf(A8, E, y[7]));
    if (!EDGE) {
        float4* o4p = reinterpret_cast<float4*>(out);
        const int idx = (ob >> 2) + 2 * l;
        o4p[idx]     = make_float4(o0, o1, o2, o3);
        o4p[idx + 1] = make_float4(o4, o5, o6, o7);
    } else {
        const int oi = ob + 8 * l;
        const int zf = n - kSkip;                // outputs at/after this are 0
        float v[8] = {o0, o1, o2, o3, o4, o5, o6, o7};
        #pragma unroll
        for (int e = 0; e < 8; ++e)
            if (oi + e < nout)
                out[oi + e] = (oi + e < zf) ? v[e] : 0.0f;
    }
}

template <bool EDGE>
__device__ __forceinline__ void warp_body(const float* __restrict__ x,
                                          float* __restrict__ out,
                                          int n, int nout, int O, int l)
{
    const unsigned FULL = 0xffffffffu;

    // ---- all loads up front (MLP ~8) ----
    // warmup: 128 samples x[O-40 .. O+88); head terms x[O+88..91) uniform.
    float4 wm = ld4<EDGE>(x, O - 40 + 4 * l, n);
    float4 hd = ld4<EDGE>(x, O + 88, n);               // uniform line
    float4 u[kWpw], v[kWpw];
    #pragma unroll
    for (int j = 0; j < kWpw; ++j) {
        const int base = O + kWin * j + 88 + 8 * l;
        u[j] = ld4<EDGE>(x, base, n);
        v[j] = ld4<EDGE>(x, base + 4, n);
    }
    float4 ext = ld4<EDGE>(x, O + kWin * kWpw + 88, n);  // uniform line

    // ---- per-lane constants ----
    float c8l = 1.0f;                    // c^(8l)
    if (l & 1)  c8l *= W1;
    if (l & 2)  c8l *= W2;
    if (l & 4)  c8l *= W3;
    if (l & 8)  c8l *= W4;
    if (l & 16) c8l *= W5;
    const int m = 31 - l;
    float c4m = C3;                      // c^(127-4l) = c^3 * c^(4m)
    if (m & 1)  c4m *= V1;
    if (m & 2)  c4m *= V2;
    if (m & 4)  c4m *= V3;
    if (m & 8)  c4m *= V4;
    if (m & 16) c4m *= V5;

    // ---- warmup state: E = sum_{d=0}^{127} c^d x[O+90-d] ----
    float q = fmaf(C1, fmaf(C1, fmaf(C1, wm.x, wm.y), wm.z), wm.w);
    float p = q * c4m;
    p += __shfl_xor_sync(FULL, p, 16);
    p += __shfl_xor_sync(FULL, p, 8);
    p += __shfl_xor_sync(FULL, p, 4);
    p += __shfl_xor_sync(FULL, p, 2);
    p += __shfl_xor_sync(FULL, p, 1);
    float S = p + fmaf(C2, hd.x, fmaf(C1, hd.y, hd.z));

    // ---- 3 windows, carried in registers ----
    const int src = (l + 1) & 31;
    #pragma unroll
    for (int j = 0; j < kWpw; ++j) {
        // realign +3: next lane's u.{x,y,z}; lane 31 takes next window's lane-0 u
        // (or ext, uniform) via select-then-shfl.
        float tx = (l == 0) ? ((j < kWpw - 1) ? u[j + 1].x : ext.x) : u[j].x;
        float ty = (l == 0) ? ((j < kWpw - 1) ? u[j + 1].y : ext.y) : u[j].y;
        float tz = (l == 0) ? ((j < kWpw - 1) ? u[j + 1].z : ext.z) : u[j].z;
        float nx = __shfl_sync(FULL, tx, src);
        float ny = __shfl_sync(FULL, ty, src);
        float nz = __shfl_sync(FULL, tz, src);

        float y[8];
        scan8(u[j], v[j], nx, ny, nz, y);
        float pex, P31;
        ks4(y[7], l, pex, P31);

        float E = fmaf(c8l, S, pex);
        S = P31;                         // c^256 * S term ~ 1e-19: dropped
        emit<EDGE>(out, y, E, O + j * kWin, l, n, nout);
    }
}

__global__ __launch_bounds__(kThreads, 5)
void preemph_f32_kernel(const float* __restrict__ x, float* __restrict__ out,
                        int n, int nout)
{
    const int wid = (blockIdx.x * kThreads + threadIdx.x) >> 5;
    const int l   = threadIdx.x & 31;
    const int O   = wid * kSeg;
    if (O >= nout) return;
    // interior: warmup load O-40 >= 0; max read O + kSeg + 91 < n;
    // outputs [O, O+kSeg) inside nout and before the zero tail (n-91).
    const bool edge = (O == 0) || (O + kSeg + 92 > n) || (O + kSeg > nout)
                   || (O + kSeg > n - kSkip);
    if (edge) warp_body<true >(x, out, n, nout, O, l);
    else      warp_body<false>(x, out, n, nout, O, l);
}

extern "C" void kernel_launch(void* const* d_in, const int* in_sizes, int n_in,
                              void* d_out, int out_size) {
    const float* x = (const float*)d_in[0];
    float* out = (float*)d_out;
    const int n = in_sizes[0];
    const int warps = (out_size + kSeg - 1) / kSeg;
    const int grid = (warps + (kThreads / 32) - 1) / (kThreads / 32);
    preemph_f32_kernel<<<grid, kThreads>>>(x, out, n, out_size);
}